// round 2
// baseline (speedup 1.0000x reference)
#include <cuda_runtime.h>
#include <cuda_bf16.h>
#include <math.h>

// ---------------------------------------------------------------------------
// MAB block: out = O + relu(O @ Wo^T + bo), where (with H=16 heads of d=64)
//   O_[h,n,:] = Q_[h,n,:] + (softmax(Q_h K_h^T)/32 @ V_h)[n,:]
//   and O = O_.reshape(-1,1024)  -- NOT the inverse of the head split:
//   O[r, j] = O_[ r/128, (r%128)*16 + j/64, j%64 ]
//   q = Q@Wq^T+bq ; k = K@Wk^T+bk ; v = K@Wv^T+bv
// All fp32. N_Q = N_K = 2048, DIM = 1024.
// ---------------------------------------------------------------------------

#define NQ 2048
#define NK 2048
#define DIM 1024
#define NHEAD 16
#define HDIM 64

// Scratch (allocation-free rule: __device__ globals)
__device__ float g_q[NQ * DIM];
__device__ float g_k[NK * DIM];
__device__ float g_v[NK * DIM];
__device__ float g_o[NQ * DIM];

// ---------------------------------------------------------------------------
// GEMM: C[M,N] = A[M,K] @ B[N,K]^T + bias[N]   (both operands K-major)
// epilogue relu_resid: C = resid + relu(acc + bias)
// 128x128 tile, BK=16, 256 threads, 8x8 per thread.
// ---------------------------------------------------------------------------
__global__ __launch_bounds__(256) void gemm_bias(
    const float* __restrict__ A, const float* __restrict__ B,
    const float* __restrict__ bias, const float* __restrict__ resid,
    float* __restrict__ C, int M, int N, int K, int relu_resid)
{
    constexpr int BM = 128, BN = 128, BK = 16;
    __shared__ float As[BK][BM + 4];
    __shared__ float Bs[BK][BN + 4];

    const int tid  = threadIdx.x;
    const int tcol = tid & 15;   // 0..15
    const int trow = tid >> 4;   // 0..15
    const int rowBase = blockIdx.y * BM;
    const int colBase = blockIdx.x * BN;
    const float* Ab = A + (size_t)rowBase * K;
    const float* Bb = B + (size_t)colBase * K;

    float acc[8][8];
#pragma unroll
    for (int i = 0; i < 8; i++)
#pragma unroll
        for (int j = 0; j < 8; j++) acc[i][j] = 0.f;

    for (int kt = 0; kt < K; kt += BK) {
#pragma unroll
        for (int u = 0; u < 2; u++) {
            int f  = tid + u * 256;       // 0..511 float4 slots
            int r  = f >> 2;              // 0..127
            int c4 = (f & 3) << 2;        // 0,4,8,12
            float4 a = *(const float4*)(Ab + (size_t)r * K + kt + c4);
            As[c4 + 0][r] = a.x; As[c4 + 1][r] = a.y;
            As[c4 + 2][r] = a.z; As[c4 + 3][r] = a.w;
            float4 b = *(const float4*)(Bb + (size_t)r * K + kt + c4);
            Bs[c4 + 0][r] = b.x; Bs[c4 + 1][r] = b.y;
            Bs[c4 + 2][r] = b.z; Bs[c4 + 3][r] = b.w;
        }
        __syncthreads();
#pragma unroll
        for (int k = 0; k < BK; k++) {
            float ra[8], rb[8];
#pragma unroll
            for (int i = 0; i < 8; i++) ra[i] = As[k][trow * 8 + i];
#pragma unroll
            for (int j = 0; j < 8; j++) rb[j] = Bs[k][tcol * 8 + j];
#pragma unroll
            for (int i = 0; i < 8; i++)
#pragma unroll
                for (int j = 0; j < 8; j++) acc[i][j] += ra[i] * rb[j];
        }
        __syncthreads();
    }

#pragma unroll
    for (int i = 0; i < 8; i++) {
        int row = rowBase + trow * 8 + i;
#pragma unroll
        for (int j = 0; j < 8; j++) {
            int col = colBase + tcol * 8 + j;
            float v = acc[i][j] + bias[col];
            if (relu_resid)
                v = resid[(size_t)row * N + col] + fmaxf(v, 0.f);
            C[(size_t)row * N + col] = v;
        }
    }
}

// ---------------------------------------------------------------------------
// Fused attention per (head, 64-row q-tile). Online softmax, scale AFTER
// softmax by 1/32 (module quirk #1), residual +Q, and the quirky reshape
// (module quirk #2) applied at the epilogue write:
//   value for (h, n, c) lands at go[h*128 + n/16][(n%16)*64 + c]
// Block: 256 threads as 16x16; each thread owns 4x4 of the 64x64 tiles.
// ---------------------------------------------------------------------------
__global__ __launch_bounds__(256) void attn_kernel(
    const float* __restrict__ gq, const float* __restrict__ gk,
    const float* __restrict__ gv, float* __restrict__ go)
{
    constexpr int D = 64, TS = 64, LD = 68;
    __shared__ float QsT[D][LD];  // [d][qrow]  (transposed)
    __shared__ float KsT[D][LD];  // [d][krow]  (transposed)
    __shared__ float Vs[TS][LD];  // [krow][d]
    __shared__ float Ps[TS][LD];  // [qrow][krow]

    const int h  = blockIdx.y;
    const int q0 = blockIdx.x * TS;
    const int c0 = h * D;            // column offset of this head
    const int tid = threadIdx.x;
    const int tx = tid & 15;         // k-col / d-col group
    const int ty = tid >> 4;         // q-row group

    // load Q tile transposed: QsT[d][r] = q[q0+r][c0+d]
#pragma unroll
    for (int u = 0; u < 4; u++) {
        int f  = tid + u * 256;      // 0..1023 float4 slots
        int r  = f >> 4;             // 0..63
        int c4 = (f & 15) << 2;      // 0..60
        float4 a = *(const float4*)(gq + (size_t)(q0 + r) * DIM + c0 + c4);
        QsT[c4 + 0][r] = a.x; QsT[c4 + 1][r] = a.y;
        QsT[c4 + 2][r] = a.z; QsT[c4 + 3][r] = a.w;
    }
    __syncthreads();

    float m_i[4], l_i[4], oacc[4][4];
#pragma unroll
    for (int i = 0; i < 4; i++) {
        m_i[i] = -1e30f; l_i[i] = 0.f;
#pragma unroll
        for (int j = 0; j < 4; j++) oacc[i][j] = 0.f;
    }

    for (int k0 = 0; k0 < NK; k0 += TS) {
        // load K tile transposed + V tile natural
#pragma unroll
        for (int u = 0; u < 4; u++) {
            int f  = tid + u * 256;
            int r  = f >> 4;
            int c4 = (f & 15) << 2;
            float4 b = *(const float4*)(gk + (size_t)(k0 + r) * DIM + c0 + c4);
            KsT[c4 + 0][r] = b.x; KsT[c4 + 1][r] = b.y;
            KsT[c4 + 2][r] = b.z; KsT[c4 + 3][r] = b.w;
            float4 v = *(const float4*)(gv + (size_t)(k0 + r) * DIM + c0 + c4);
            *(float4*)&Vs[r][c4] = v;
        }
        __syncthreads();

        // S = Q K^T : s[i][j], q-row = ty*4+i, k-row = tx*4+j
        float s[4][4];
#pragma unroll
        for (int i = 0; i < 4; i++)
#pragma unroll
            for (int j = 0; j < 4; j++) s[i][j] = 0.f;
#pragma unroll 8
        for (int d = 0; d < D; d++) {
            float4 qv = *(const float4*)&QsT[d][ty * 4];
            float4 kv = *(const float4*)&KsT[d][tx * 4];
            float qa[4] = {qv.x, qv.y, qv.z, qv.w};
            float ka[4] = {kv.x, kv.y, kv.z, kv.w};
#pragma unroll
            for (int i = 0; i < 4; i++)
#pragma unroll
                for (int j = 0; j < 4; j++) s[i][j] += qa[i] * ka[j];
        }

        // online softmax over the k dimension (row reduce across tx group)
        float alpha[4];
#pragma unroll
        for (int i = 0; i < 4; i++) {
            float rmax = fmaxf(fmaxf(s[i][0], s[i][1]), fmaxf(s[i][2], s[i][3]));
#pragma unroll
            for (int mo = 8; mo >= 1; mo >>= 1)
                rmax = fmaxf(rmax, __shfl_xor_sync(0xffffffffu, rmax, mo));
            float mn = fmaxf(m_i[i], rmax);
            alpha[i] = __expf(m_i[i] - mn);
            m_i[i] = mn;
            float rsum = 0.f;
#pragma unroll
            for (int j = 0; j < 4; j++) {
                s[i][j] = __expf(s[i][j] - mn);
                rsum += s[i][j];
            }
#pragma unroll
            for (int mo = 8; mo >= 1; mo >>= 1)
                rsum += __shfl_xor_sync(0xffffffffu, rsum, mo);
            l_i[i] = l_i[i] * alpha[i] + rsum;
#pragma unroll
            for (int j = 0; j < 4; j++) oacc[i][j] *= alpha[i];
            // stage P into smem for the PV product
            *(float4*)&Ps[ty * 4 + i][tx * 4] =
                make_float4(s[i][0], s[i][1], s[i][2], s[i][3]);
        }
        __syncthreads();

        // O += P @ V
#pragma unroll 8
        for (int kk = 0; kk < TS; kk++) {
            float4 vv = *(const float4*)&Vs[kk][tx * 4];
            float va[4] = {vv.x, vv.y, vv.z, vv.w};
            float p[4];
#pragma unroll
            for (int i = 0; i < 4; i++) p[i] = Ps[ty * 4 + i][kk];
#pragma unroll
            for (int i = 0; i < 4; i++)
#pragma unroll
                for (int j = 0; j < 4; j++) oacc[i][j] += p[i] * va[j];
        }
        __syncthreads();  // before overwriting K/V/P next iteration
    }

    // epilogue: value(h, n, c) = Q_[h,n,c] + oacc/(l*32)
    // scrambled destination (reference's reshape quirk):
    //   go[h*128 + n/16][(n%16)*64 + c]
#pragma unroll
    for (int i = 0; i < 4; i++) {
        float inv = 1.f / (l_i[i] * 32.f);   // sqrt(1024) = 32
        int n = q0 + ty * 4 + i;             // attention row
        int drow = h * 128 + (n >> 4);
        int dcolBase = (n & 15) * 64;
#pragma unroll
        for (int j = 0; j < 4; j++) {
            int c = tx * 4 + j;
            float qval = QsT[c][ty * 4 + i];
            go[(size_t)drow * DIM + dcolBase + c] = qval + oacc[i][j] * inv;
        }
    }
}

// ---------------------------------------------------------------------------
extern "C" void kernel_launch(void* const* d_in, const int* in_sizes, int n_in,
                              void* d_out, int out_size)
{
    const float* Q  = (const float*)d_in[0];
    const float* K  = (const float*)d_in[1];
    const float* Wq = (const float*)d_in[2];
    const float* bq = (const float*)d_in[3];
    const float* Wk = (const float*)d_in[4];
    const float* bk = (const float*)d_in[5];
    const float* Wv = (const float*)d_in[6];
    const float* bv = (const float*)d_in[7];
    const float* Wo = (const float*)d_in[8];
    const float* bo = (const float*)d_in[9];
    float* out = (float*)d_out;

    float *q, *k, *v, *o;
    cudaGetSymbolAddress((void**)&q, g_q);
    cudaGetSymbolAddress((void**)&k, g_k);
    cudaGetSymbolAddress((void**)&v, g_v);
    cudaGetSymbolAddress((void**)&o, g_o);

    dim3 gg(DIM / 128, NQ / 128);   // (8, 16)

    gemm_bias<<<gg, 256>>>(Q, Wq, bq, nullptr, q, NQ, DIM, DIM, 0);
    gemm_bias<<<gg, 256>>>(K, Wk, bk, nullptr, k, NK, DIM, DIM, 0);
    gemm_bias<<<gg, 256>>>(K, Wv, bv, nullptr, v, NK, DIM, DIM, 0);

    attn_kernel<<<dim3(NQ / 64, NHEAD), 256>>>(q, k, v, o);

    gemm_bias<<<gg, 256>>>(o, Wo, bo, o, out, NQ, DIM, DIM, 1);
}

// round 4
// speedup vs baseline: 2.5689x; 2.5689x over previous
#include <cuda_runtime.h>
#include <cuda_bf16.h>
#include <math.h>

// ---------------------------------------------------------------------------
// MAB block, bf16x2 split-precision tensor cores (m16n8k16, 3-mma per k16):
//   q = Q@Wq^T+bq ; k = K@Wk^T+bk ; v = K@Wv^T+bv
//   per head h (16 heads, d=64):
//     O_[h,n,:] = Q_[h,n,:] + (softmax(Q_h K_h^T)/32 @ V_h)[n,:]
//   reshape quirk: O[r,j] = O_[ r/128, (r%128)*16 + j/64, j%64 ]
//   out = O + relu(O@Wo^T + bo)
// ---------------------------------------------------------------------------

#define NQ 2048
#define NK 2048
#define DIM 1024
#define NHEAD 16
#define HD 64
#define PD 512          // u32 pairs per 1024-wide row
#define NKP 1024        // u32 pairs per 2048-wide row (vt)

// fp32 scratch
__device__ float g_q[NQ * DIM];
__device__ float g_v[NK * DIM];
__device__ float g_o[NQ * DIM];
// bf16 hi/lo planes (u32 = bf16x2 pair, element0 = even index)
__device__ unsigned g_Qihi[NQ * PD],  g_Qilo[NQ * PD];    // packed input Q
__device__ unsigned g_Kihi[NK * PD],  g_Kilo[NK * PD];    // packed input K
__device__ unsigned g_wqhi[DIM * PD], g_wqlo[DIM * PD];
__device__ unsigned g_wkhi[DIM * PD], g_wklo[DIM * PD];
__device__ unsigned g_wvhi[DIM * PD], g_wvlo[DIM * PD];
__device__ unsigned g_wohi[DIM * PD], g_wolo[DIM * PD];
__device__ unsigned g_khi[NK * PD],   g_klo[NK * PD];     // k activation
__device__ unsigned g_vthi[DIM * NKP], g_vtlo[DIM * NKP]; // v transposed
__device__ unsigned g_ohi[NQ * PD],   g_olo[NQ * PD];     // attention out

// ---------------------------------------------------------------------------
__device__ __forceinline__ void split_pair(float a, float b,
                                           unsigned& hi, unsigned& lo) {
    unsigned h;
    asm("cvt.rn.bf16x2.f32 %0, %1, %2;" : "=r"(h) : "f"(b), "f"(a)); // lo16=a
    float ha = __uint_as_float(h << 16);
    float hb = __uint_as_float(h & 0xffff0000u);
    unsigned l;
    float ra = a - ha, rb = b - hb;
    asm("cvt.rn.bf16x2.f32 %0, %1, %2;" : "=r"(l) : "f"(rb), "f"(ra));
    hi = h; lo = l;
}

__device__ __forceinline__ void mma_bf16(float* c, const unsigned* a,
                                         unsigned b0, unsigned b1) {
    asm volatile(
        "mma.sync.aligned.m16n8k16.row.col.f32.bf16.bf16.f32 "
        "{%0,%1,%2,%3},{%4,%5,%6,%7},{%8,%9},{%0,%1,%2,%3};"
        : "+f"(c[0]), "+f"(c[1]), "+f"(c[2]), "+f"(c[3])
        : "r"(a[0]), "r"(a[1]), "r"(a[2]), "r"(a[3]), "r"(b0), "r"(b1));
}

// e^x via FMA-only exp2 (no MUFU). Valid x <= 0 (clamped at -80). err ~2.4e-6.
__device__ __forceinline__ float fexp(float x) {
    float z = fmaxf(x, -80.f) * 1.44269504f;
    float t = z + 12582912.0f;                    // round-to-nearest in mantissa
    int   r = __float_as_int(t) - 0x4B400000;     // (int)round(z)
    float f = z - (t - 12582912.0f);              // frac in [-0.5,0.5]
    float p = 1.0f + f * (0.69314718f + f * (0.24022650f + f * (0.05550411f
                  + f * (0.00961804f + f * 0.00133336f))));
    return __int_as_float(__float_as_int(p) + (r << 23));
}

__device__ __forceinline__ void cp16(unsigned dst, const void* src) {
    asm volatile("cp.async.cg.shared.global [%0], [%1], 16;" :: "r"(dst), "l"(src));
}
#define CP_COMMIT asm volatile("cp.async.commit_group;")
#define CP_WAIT1  asm volatile("cp.async.wait_group 1;")
#define CP_WAIT0  asm volatile("cp.async.wait_group 0;")

// ---------------------------------------------------------------------------
// pack fp32 -> bf16 hi/lo planes
// ---------------------------------------------------------------------------
__global__ void pack_split(const float* __restrict__ src,
                           unsigned* __restrict__ hi, unsigned* __restrict__ lo,
                           int npairs)
{
    int i = blockIdx.x * blockDim.x + threadIdx.x;
    if (i < npairs) {
        float2 v = ((const float2*)src)[i];
        unsigned h, l;
        split_pair(v.x, v.y, h, l);
        hi[i] = h; lo[i] = l;
    }
}

// v[n][c] fp32 -> vt planes [c][n-pair]
__global__ void packT_v(const float* __restrict__ v,
                        unsigned* __restrict__ vthi, unsigned* __restrict__ vtlo)
{
    __shared__ float t[32][33];
    int n0 = blockIdx.x * 32, c0 = blockIdx.y * 32;
    int tid = threadIdx.x;
#pragma unroll
    for (int u = 0; u < 4; u++) {
        int e = tid + u * 256, r = e >> 5, c = e & 31;
        t[r][c] = v[(size_t)(n0 + r) * DIM + c0 + c];
    }
    __syncthreads();
#pragma unroll
    for (int u = 0; u < 2; u++) {
        int e = tid + u * 256, cr = e >> 4, p = e & 15;
        unsigned h, l;
        split_pair(t[2 * p][cr], t[2 * p + 1][cr], h, l);
        size_t idx = (size_t)(c0 + cr) * NKP + n0 / 2 + p;
        vthi[idx] = h; vtlo[idx] = l;
    }
}

// ---------------------------------------------------------------------------
// GEMM: C[2048,1024] = A[2048,1024] @ B[1024,1024]^T + bias
// A,B given as bf16 hi/lo pair planes. 3-mma split accumulate (hh, hl, lh).
// BM=128 BN=128 BK=32, 256 thr, 8 warps (2m x 4n), warp tile 64x32.
// mode 0: write fp32    mode 1: write planes    mode 2: fp32 = resid+relu(acc)
// ---------------------------------------------------------------------------
#define GLD 20                       // u32 words per 16-pair smem row
#define ABUF (128 * GLD)             // 2560 u32 per plane-buffer
#define GEMM_SMEM (8 * ABUF * 4)     // 81920 B

__global__ __launch_bounds__(256) void gemm_bf16x2(
    const unsigned* __restrict__ Ahi, const unsigned* __restrict__ Alo,
    const unsigned* __restrict__ Bhi, const unsigned* __restrict__ Blo,
    const float* __restrict__ bias, const float* __restrict__ resid,
    float* __restrict__ Cf, unsigned* __restrict__ Chi, unsigned* __restrict__ Clo,
    int mode)
{
    extern __shared__ unsigned smu[];
    const unsigned sbase = (unsigned)__cvta_generic_to_shared(smu);

    const int tid  = threadIdx.x;
    const int warp = tid >> 5;
    const int lane = tid & 31;
    const int g = lane >> 2;
    const int q = lane & 3;
    const int wm = warp & 1;
    const int wn = warp >> 1;
    const int rowBase = blockIdx.y * 128;
    const int colBase = blockIdx.x * 128;

    auto issue = [&](int kt) {
        int buf = kt & 1;
        const unsigned* srcs[4] = {Ahi, Alo, Bhi, Blo};
#pragma unroll
        for (int p = 0; p < 4; p++) {
            int base = (p < 2) ? rowBase : colBase;
            unsigned soff = ((p < 2 ? buf * 2 + p : 4 + buf * 2 + (p - 2)) * ABUF);
#pragma unroll
            for (int u = 0; u < 2; u++) {
                int e = tid + u * 256;        // 0..511
                int row = e >> 2, ch = (e & 3) * 4;
                cp16(sbase + (soff + row * GLD + ch) * 4,
                     srcs[p] + (size_t)(base + row) * PD + kt * 16 + ch);
            }
        }
        CP_COMMIT;
    };

    float acc[16][4];
#pragma unroll
    for (int i = 0; i < 16; i++)
#pragma unroll
        for (int j = 0; j < 4; j++) acc[i][j] = 0.f;

    issue(0);
    const int NKT = DIM / 32;        // 32
    for (int kt = 0; kt < NKT; kt++) {
        if (kt + 1 < NKT) { issue(kt + 1); CP_WAIT1; }
        else              { CP_WAIT0; }
        __syncthreads();
        int buf = kt & 1;
        const unsigned* Ah = smu + (buf * 2 + 0) * ABUF;
        const unsigned* Al = smu + (buf * 2 + 1) * ABUF;
        const unsigned* Bh = smu + (4 + buf * 2 + 0) * ABUF;
        const unsigned* Bl = smu + (4 + buf * 2 + 1) * ABUF;

#pragma unroll
        for (int ks = 0; ks < 2; ks++) {
            int pb = ks * 8;
            unsigned ah[4][4], al[4][4];
#pragma unroll
            for (int mt = 0; mt < 4; mt++) {
                int r0 = wm * 64 + mt * 16 + g;
                ah[mt][0] = Ah[r0 * GLD + pb + q];
                ah[mt][1] = Ah[(r0 + 8) * GLD + pb + q];
                ah[mt][2] = Ah[r0 * GLD + pb + q + 4];
                ah[mt][3] = Ah[(r0 + 8) * GLD + pb + q + 4];
                al[mt][0] = Al[r0 * GLD + pb + q];
                al[mt][1] = Al[(r0 + 8) * GLD + pb + q];
                al[mt][2] = Al[r0 * GLD + pb + q + 4];
                al[mt][3] = Al[(r0 + 8) * GLD + pb + q + 4];
            }
            unsigned bh[4][2], bl[4][2];
#pragma unroll
            for (int nt = 0; nt < 4; nt++) {
                int n0 = wn * 32 + nt * 8 + g;
                bh[nt][0] = Bh[n0 * GLD + pb + q];
                bh[nt][1] = Bh[n0 * GLD + pb + q + 4];
                bl[nt][0] = Bl[n0 * GLD + pb + q];
                bl[nt][1] = Bl[n0 * GLD + pb + q + 4];
            }
#pragma unroll
            for (int mt = 0; mt < 4; mt++)
#pragma unroll
                for (int nt = 0; nt < 4; nt++) {
                    mma_bf16(acc[mt * 4 + nt], ah[mt], bh[nt][0], bh[nt][1]);
                    mma_bf16(acc[mt * 4 + nt], ah[mt], bl[nt][0], bl[nt][1]);
                    mma_bf16(acc[mt * 4 + nt], al[mt], bh[nt][0], bh[nt][1]);
                }
        }
        __syncthreads();
    }

#pragma unroll
    for (int mt = 0; mt < 4; mt++) {
#pragma unroll
        for (int nt = 0; nt < 4; nt++) {
            float* a = acc[mt * 4 + nt];
            int row = rowBase + wm * 64 + mt * 16 + g;
            int col = colBase + wn * 32 + nt * 8 + 2 * q;
            float b0 = bias[col], b1 = bias[col + 1];
#pragma unroll
            for (int half = 0; half < 2; half++) {
                int r = row + half * 8;
                float v0 = a[half * 2 + 0] + b0;
                float v1 = a[half * 2 + 1] + b1;
                if (mode == 2) {
                    const float* rp = resid + (size_t)r * DIM + col;
                    v0 = rp[0] + fmaxf(v0, 0.f);
                    v1 = rp[1] + fmaxf(v1, 0.f);
                }
                if (mode == 1) {
                    unsigned h, l;
                    split_pair(v0, v1, h, l);
                    Chi[(size_t)r * PD + col / 2] = h;
                    Clo[(size_t)r * PD + col / 2] = l;
                } else {
                    *(float2*)(Cf + (size_t)r * DIM + col) = make_float2(v0, v1);
                }
            }
        }
    }
}

// ---------------------------------------------------------------------------
// Attention: block = (head h, 128 q rows), 256 thr, bf16x2 split everywhere,
// FMA-only exp. K/V tiles (64 keys) cp.async double-buffered.
// smem (u32): Phi[128][36] Plo[128][36] (overlaid by Q fp32 [128][68] at init)
//             then {Khi,Klo,Vhi,Vlo}[64][36] x 2 buffers
// ---------------------------------------------------------------------------
#define PLD 36
#define PREG (128 * PLD)             // one P plane
#define KLD 36
#define KVT (64 * KLD)               // one K/V plane tile
#define KVOFF (2 * PREG)             // 9216 u32
#define ATTN_SMEM ((2 * PREG + 8 * KVT) * 4)   // 110592 B

__global__ __launch_bounds__(256) void attn_bf16x2(
    const float* __restrict__ gq,
    const unsigned* __restrict__ khi, const unsigned* __restrict__ klo,
    const unsigned* __restrict__ vthi, const unsigned* __restrict__ vtlo,
    float* __restrict__ go, unsigned* __restrict__ ohi, unsigned* __restrict__ olo)
{
    extern __shared__ unsigned smu[];
    const unsigned sbase = (unsigned)__cvta_generic_to_shared(smu);
    unsigned* Phi = smu;
    unsigned* Plo = smu + PREG;
    float* Qst = (float*)smu;        // [128][68] fp32, overlays P region

    const int h  = blockIdx.y;
    const int q0 = blockIdx.x * 128;
    const int c0 = h * HD;
    const int tid  = threadIdx.x;
    const int warp = tid >> 5;
    const int lane = tid & 31;
    const int g = lane >> 2;
    const int q = lane & 3;
    const int wrow = warp * 16;

    auto issue = [&](int kb) {
        int buf = kb & 1;
        int k0 = kb * 64;
        const unsigned* srcs[4] = {khi, klo, vthi, vtlo};
#pragma unroll
        for (int p = 0; p < 4; p++) {
            unsigned soff = KVOFF + (buf * 4 + p) * KVT;
#pragma unroll
            for (int u = 0; u < 2; u++) {
                int e = tid + u * 256;     // 0..511
                int row = e >> 3, ch = (e & 7) * 4;
                size_t gidx = (p < 2)
                    ? (size_t)(k0 + row) * PD + h * 32 + ch
                    : (size_t)(c0 + row) * NKP + kb * 32 + ch;
                cp16(sbase + (soff + row * KLD + ch) * 4, srcs[p] + gidx);
            }
        }
        CP_COMMIT;
    };

    issue(0);        // overlap K/V load with Q staging

    // stage Q fp32 into smem
#pragma unroll
    for (int u = 0; u < 8; u++) {
        int f = tid + u * 256;            // 2048 float4 slots
        int r = f >> 4, c4 = (f & 15) << 2;
        float4 a = *(const float4*)(gq + (size_t)(q0 + r) * DIM + c0 + c4);
        *(float4*)&Qst[r * 68 + c4] = a;
    }
    __syncthreads();

    // build Q bf16x2 fragments (4 k16-steps)
    unsigned qh[4][4], ql[4][4];
#pragma unroll
    for (int s = 0; s < 4; s++) {
        int cb = s * 16 + 2 * q;
        float2 p00 = *(float2*)&Qst[(wrow + g) * 68 + cb];
        float2 p10 = *(float2*)&Qst[(wrow + g + 8) * 68 + cb];
        float2 p01 = *(float2*)&Qst[(wrow + g) * 68 + cb + 8];
        float2 p11 = *(float2*)&Qst[(wrow + g + 8) * 68 + cb + 8];
        split_pair(p00.x, p00.y, qh[s][0], ql[s][0]);
        split_pair(p10.x, p10.y, qh[s][1], ql[s][1]);
        split_pair(p01.x, p01.y, qh[s][2], ql[s][2]);
        split_pair(p11.x, p11.y, qh[s][3], ql[s][3]);
    }
    __syncthreads();

    float m0 = -1e30f, m1 = -1e30f, l0 = 0.f, l1 = 0.f;
    float oacc[8][4];
#pragma unroll
    for (int nt = 0; nt < 8; nt++)
#pragma unroll
        for (int j = 0; j < 4; j++) oacc[nt][j] = 0.f;

    const int NKB = NK / 64;             // 32
    for (int kb = 0; kb < NKB; kb++) {
        if (kb + 1 < NKB) { issue(kb + 1); CP_WAIT1; }
        else              { CP_WAIT0; }
        __syncthreads();
        int buf = kb & 1;
        const unsigned* Kh = smu + KVOFF + (buf * 4 + 0) * KVT;
        const unsigned* Kl = smu + KVOFF + (buf * 4 + 1) * KVT;
        const unsigned* Vh = smu + KVOFF + (buf * 4 + 2) * KVT;
        const unsigned* Vl = smu + KVOFF + (buf * 4 + 3) * KVT;

        // S = Q K^T (3-mma split)
        float sacc[8][4];
#pragma unroll
        for (int nt = 0; nt < 8; nt++)
#pragma unroll
            for (int j = 0; j < 4; j++) sacc[nt][j] = 0.f;
#pragma unroll
        for (int ks = 0; ks < 4; ks++) {
            int pb = ks * 8;
#pragma unroll
            for (int nt = 0; nt < 8; nt++) {
                int kr = nt * 8 + g;
                unsigned bh0 = Kh[kr * KLD + pb + q];
                unsigned bh1 = Kh[kr * KLD + pb + q + 4];
                unsigned bl0 = Kl[kr * KLD + pb + q];
                unsigned bl1 = Kl[kr * KLD + pb + q + 4];
                mma_bf16(sacc[nt], qh[ks], bh0, bh1);
                mma_bf16(sacc[nt], qh[ks], bl0, bl1);
                mma_bf16(sacc[nt], ql[ks], bh0, bh1);
            }
        }

        // online softmax (FMA-only exp)
        float mx0 = -1e30f, mx1 = -1e30f;
#pragma unroll
        for (int nt = 0; nt < 8; nt++) {
            mx0 = fmaxf(mx0, fmaxf(sacc[nt][0], sacc[nt][1]));
            mx1 = fmaxf(mx1, fmaxf(sacc[nt][2], sacc[nt][3]));
        }
        mx0 = fmaxf(mx0, __shfl_xor_sync(0xffffffffu, mx0, 1));
        mx0 = fmaxf(mx0, __shfl_xor_sync(0xffffffffu, mx0, 2));
        mx1 = fmaxf(mx1, __shfl_xor_sync(0xffffffffu, mx1, 1));
        mx1 = fmaxf(mx1, __shfl_xor_sync(0xffffffffu, mx1, 2));
        float nm0 = fmaxf(m0, mx0), nm1 = fmaxf(m1, mx1);
        float al0 = fexp(m0 - nm0), al1 = fexp(m1 - nm1);
        m0 = nm0; m1 = nm1;

        float s0 = 0.f, s1 = 0.f;
#pragma unroll
        for (int nt = 0; nt < 8; nt++) {
            sacc[nt][0] = fexp(sacc[nt][0] - nm0);
            sacc[nt][1] = fexp(sacc[nt][1] - nm0);
            sacc[nt][2] = fexp(sacc[nt][2] - nm1);
            sacc[nt][3] = fexp(sacc[nt][3] - nm1);
            s0 += sacc[nt][0] + sacc[nt][1];
            s1 += sacc[nt][2] + sacc[nt][3];
        }
        s0 += __shfl_xor_sync(0xffffffffu, s0, 1);
        s0 += __shfl_xor_sync(0xffffffffu, s0, 2);
        s1 += __shfl_xor_sync(0xffffffffu, s1, 1);
        s1 += __shfl_xor_sync(0xffffffffu, s1, 2);
        l0 = l0 * al0 + s0;
        l1 = l1 * al1 + s1;
#pragma unroll
        for (int nt = 0; nt < 8; nt++) {
            oacc[nt][0] *= al0; oacc[nt][1] *= al0;
            oacc[nt][2] *= al1; oacc[nt][3] *= al1;
        }

        // stage P split into warp-private smem rows
        __syncwarp();
#pragma unroll
        for (int nt = 0; nt < 8; nt++) {
            unsigned h2, l2;
            split_pair(sacc[nt][0], sacc[nt][1], h2, l2);
            Phi[(wrow + g) * PLD + nt * 4 + q] = h2;
            Plo[(wrow + g) * PLD + nt * 4 + q] = l2;
            split_pair(sacc[nt][2], sacc[nt][3], h2, l2);
            Phi[(wrow + g + 8) * PLD + nt * 4 + q] = h2;
            Plo[(wrow + g + 8) * PLD + nt * 4 + q] = l2;
        }
        __syncwarp();

        // O += P V (3-mma split)
#pragma unroll
        for (int ks = 0; ks < 4; ks++) {
            int pb = ks * 8;
            unsigned pah[4], pal[4];
            pah[0] = Phi[(wrow + g) * PLD + pb + q];
            pah[1] = Phi[(wrow + g + 8) * PLD + pb + q];
            pah[2] = Phi[(wrow + g) * PLD + pb + q + 4];
            pah[3] = Phi[(wrow + g + 8) * PLD + pb + q + 4];
            pal[0] = Plo[(wrow + g) * PLD + pb + q];
            pal[1] = Plo[(wrow + g + 8) * PLD + pb + q];
            pal[2] = Plo[(wrow + g) * PLD + pb + q + 4];
            pal[3] = Plo[(wrow + g + 8) * PLD + pb + q + 4];
#pragma unroll
            for (int nt = 0; nt < 8; nt++) {
                int dr = nt * 8 + g;
                unsigned bh0 = Vh[dr * KLD + pb + q];
                unsigned bh1 = Vh[dr * KLD + pb + q + 4];
                unsigned bl0 = Vl[dr * KLD + pb + q];
                unsigned bl1 = Vl[dr * KLD + pb + q + 4];
                mma_bf16(oacc[nt], pah, bh0, bh1);
                mma_bf16(oacc[nt], pah, bl0, bl1);
                mma_bf16(oacc[nt], pal, bh0, bh1);
            }
        }
        __syncthreads();   // protect K/V buffers before next issue
    }

    // epilogue: /(l*32), +Q residual, scrambled reshape, fp32 + packed planes
    float inv0 = 1.f / (l0 * 32.f);
    float inv1 = 1.f / (l1 * 32.f);
    int n0r = q0 + wrow + g;
    int n1r = n0r + 8;
    int dr0 = h * 128 + (n0r >> 4), dc0 = (n0r & 15) * 64;
    int dr1 = h * 128 + (n1r >> 4), dc1 = (n1r & 15) * 64;
#pragma unroll
    for (int nt = 0; nt < 8; nt++) {
        int c = nt * 8 + 2 * q;
        float2 qr0 = *(const float2*)(gq + (size_t)n0r * DIM + c0 + c);
        float2 qr1 = *(const float2*)(gq + (size_t)n1r * DIM + c0 + c);
        float o0x = qr0.x + oacc[nt][0] * inv0;
        float o0y = qr0.y + oacc[nt][1] * inv0;
        float o1x = qr1.x + oacc[nt][2] * inv1;
        float o1y = qr1.y + oacc[nt][3] * inv1;
        *(float2*)(go + (size_t)dr0 * DIM + dc0 + c) = make_float2(o0x, o0y);
        *(float2*)(go + (size_t)dr1 * DIM + dc1 + c) = make_float2(o1x, o1y);
        unsigned hh, ll;
        split_pair(o0x, o0y, hh, ll);
        ohi[(size_t)dr0 * PD + (dc0 + c) / 2] = hh;
        olo[(size_t)dr0 * PD + (dc0 + c) / 2] = ll;
        split_pair(o1x, o1y, hh, ll);
        ohi[(size_t)dr1 * PD + (dc1 + c) / 2] = hh;
        olo[(size_t)dr1 * PD + (dc1 + c) / 2] = ll;
    }
}

// ---------------------------------------------------------------------------
extern "C" void kernel_launch(void* const* d_in, const int* in_sizes, int n_in,
                              void* d_out, int out_size)
{
    const float* Q  = (const float*)d_in[0];
    const float* K  = (const float*)d_in[1];
    const float* Wq = (const float*)d_in[2];
    const float* bq = (const float*)d_in[3];
    const float* Wk = (const float*)d_in[4];
    const float* bk = (const float*)d_in[5];
    const float* Wv = (const float*)d_in[6];
    const float* bv = (const float*)d_in[7];
    const float* Wo = (const float*)d_in[8];
    const float* bo = (const float*)d_in[9];
    float* out = (float*)d_out;

    float *q, *v, *o;
    unsigned *Qihi, *Qilo, *Kihi, *Kilo, *wqhi, *wqlo, *wkhi, *wklo;
    unsigned *wvhi, *wvlo, *wohi, *wolo, *khi, *klo, *vthi, *vtlo, *ohi, *olo;
    cudaGetSymbolAddress((void**)&q,    g_q);
    cudaGetSymbolAddress((void**)&v,    g_v);
    cudaGetSymbolAddress((void**)&o,    g_o);
    cudaGetSymbolAddress((void**)&Qihi, g_Qihi);
    cudaGetSymbolAddress((void**)&Qilo, g_Qilo);
    cudaGetSymbolAddress((void**)&Kihi, g_Kihi);
    cudaGetSymbolAddress((void**)&Kilo, g_Kilo);
    cudaGetSymbolAddress((void**)&wqhi, g_wqhi);
    cudaGetSymbolAddress((void**)&wqlo, g_wqlo);
    cudaGetSymbolAddress((void**)&wkhi, g_wkhi);
    cudaGetSymbolAddress((void**)&wklo, g_wklo);
    cudaGetSymbolAddress((void**)&wvhi, g_wvhi);
    cudaGetSymbolAddress((void**)&wvlo, g_wvlo);
    cudaGetSymbolAddress((void**)&wohi, g_wohi);
    cudaGetSymbolAddress((void**)&wolo, g_wolo);
    cudaGetSymbolAddress((void**)&khi,  g_khi);
    cudaGetSymbolAddress((void**)&klo,  g_klo);
    cudaGetSymbolAddress((void**)&vthi, g_vthi);
    cudaGetSymbolAddress((void**)&vtlo, g_vtlo);
    cudaGetSymbolAddress((void**)&ohi,  g_ohi);
    cudaGetSymbolAddress((void**)&olo,  g_olo);

    cudaFuncSetAttribute(gemm_bf16x2, cudaFuncAttributeMaxDynamicSharedMemorySize, GEMM_SMEM);
    cudaFuncSetAttribute(attn_bf16x2, cudaFuncAttributeMaxDynamicSharedMemorySize, ATTN_SMEM);

    const int actPairs = NQ * PD;    // 1M
    const int wPairs   = DIM * PD;   // 512K
    pack_split<<<actPairs / 256, 256>>>(Q,  Qihi, Qilo, actPairs);
    pack_split<<<actPairs / 256, 256>>>(K,  Kihi, Kilo, actPairs);
    pack_split<<<wPairs / 256, 256>>>(Wq, wqhi, wqlo, wPairs);
    pack_split<<<wPairs / 256, 256>>>(Wk, wkhi, wklo, wPairs);
    pack_split<<<wPairs / 256, 256>>>(Wv, wvhi, wvlo, wPairs);
    pack_split<<<wPairs / 256, 256>>>(Wo, wohi, wolo, wPairs);

    dim3 gg(DIM / 128, NQ / 128);    // (8, 16)
    gemm_bf16x2<<<gg, 256, GEMM_SMEM>>>(Qihi, Qilo, wqhi, wqlo, bq, nullptr, q, nullptr, nullptr, 0);
    gemm_bf16x2<<<gg, 256, GEMM_SMEM>>>(Kihi, Kilo, wkhi, wklo, bk, nullptr, nullptr, khi, klo, 1);
    gemm_bf16x2<<<gg, 256, GEMM_SMEM>>>(Kihi, Kilo, wvhi, wvlo, bv, nullptr, v, nullptr, nullptr, 0);

    packT_v<<<dim3(NK / 32, DIM / 32), 256>>>(v, vthi, vtlo);

    attn_bf16x2<<<dim3(NQ / 128, NHEAD), 256, ATTN_SMEM>>>(q, khi, klo, vthi, vtlo, o, ohi, olo);

    gemm_bf16x2<<<gg, 256, GEMM_SMEM>>>(ohi, olo, wohi, wolo, bo, o, out, nullptr, nullptr, 2);
}

// round 6
// speedup vs baseline: 2.6989x; 1.0506x over previous
#include <cuda_runtime.h>
#include <cuda_bf16.h>
#include <math.h>

// ---------------------------------------------------------------------------
// MAB block, bf16x2 split-precision mma.sync (tcgen05 blocked by harness
// compile target sm_103-without-a; verified R5).
//   q = Q@Wq^T+bq ; k = K@Wk^T+bk ; v = K@Wv^T+bv
//   per head h (16 heads, d=64):
//     O_[h,n,:] = Q_[h,n,:] + (softmax(Q_h K_h^T)/32 @ V_h)[n,:]
//   reshape quirk: O[r,j] = O_[ r/128, (r%128)*16 + j/64, j%64 ]
//   out = O + relu(O@Wo^T + bo)
// ---------------------------------------------------------------------------

#define NQ 2048
#define NK 2048
#define DIM 1024
#define NHEAD 16
#define HD 64
#define PD 512          // u32 pairs per 1024-wide row
#define NKP 1024        // u32 pairs per 2048-wide row (vt)

// fp32 scratch
__device__ float g_q[NQ * DIM];
__device__ float g_o[NQ * DIM];
// bf16 hi/lo planes (u32 = bf16x2 pair, element0 = even index)
__device__ unsigned g_Qihi[NQ * PD],  g_Qilo[NQ * PD];
__device__ unsigned g_Kihi[NK * PD],  g_Kilo[NK * PD];
__device__ unsigned g_wqhi[DIM * PD], g_wqlo[DIM * PD];
__device__ unsigned g_wkhi[DIM * PD], g_wklo[DIM * PD];
__device__ unsigned g_wvhi[DIM * PD], g_wvlo[DIM * PD];
__device__ unsigned g_wohi[DIM * PD], g_wolo[DIM * PD];
__device__ unsigned g_khi[NK * PD],   g_klo[NK * PD];
__device__ unsigned g_vthi[DIM * NKP], g_vtlo[DIM * NKP];
__device__ unsigned g_ohi[NQ * PD],   g_olo[NQ * PD];

// ---------------------------------------------------------------------------
__device__ __forceinline__ void split_pair(float a, float b,
                                           unsigned& hi, unsigned& lo) {
    unsigned h;
    asm("cvt.rn.bf16x2.f32 %0, %1, %2;" : "=r"(h) : "f"(b), "f"(a));
    float ha = __uint_as_float(h << 16);
    float hb = __uint_as_float(h & 0xffff0000u);
    unsigned l;
    float ra = a - ha, rb = b - hb;
    asm("cvt.rn.bf16x2.f32 %0, %1, %2;" : "=r"(l) : "f"(rb), "f"(ra));
    hi = h; lo = l;
}

__device__ __forceinline__ void mma_bf16(float* c, const unsigned* a,
                                         unsigned b0, unsigned b1) {
    asm volatile(
        "mma.sync.aligned.m16n8k16.row.col.f32.bf16.bf16.f32 "
        "{%0,%1,%2,%3},{%4,%5,%6,%7},{%8,%9},{%0,%1,%2,%3};"
        : "+f"(c[0]), "+f"(c[1]), "+f"(c[2]), "+f"(c[3])
        : "r"(a[0]), "r"(a[1]), "r"(a[2]), "r"(a[3]), "r"(b0), "r"(b1));
}

// e^x via FMA-only exp2 (no MUFU). Valid x <= 0 (clamped at -80).
__device__ __forceinline__ float fexp(float x) {
    float z = fmaxf(x, -80.f) * 1.44269504f;
    float t = z + 12582912.0f;
    int   r = __float_as_int(t) - 0x4B400000;
    float f = z - (t - 12582912.0f);
    float p = 1.0f + f * (0.69314718f + f * (0.24022650f + f * (0.05550411f
                  + f * (0.00961804f + f * 0.00133336f))));
    return __int_as_float(__float_as_int(p) + (r << 23));
}

__device__ __forceinline__ void cp16(unsigned dst, const void* src) {
    asm volatile("cp.async.cg.shared.global [%0], [%1], 16;" :: "r"(dst), "l"(src));
}
#define CP_COMMIT asm volatile("cp.async.commit_group;")
#define CP_WAIT1  asm volatile("cp.async.wait_group 1;")
#define CP_WAIT0  asm volatile("cp.async.wait_group 0;")

// ---------------------------------------------------------------------------
// Fused pack: 8 uniform segments of 512K float2-pairs each.
//   seg 0,1: Q    seg 2,3: K    seg 4: Wq  5: Wk  6: Wv  7: Wo
// ---------------------------------------------------------------------------
#define SEGP 524288
__global__ void pack_all(const float* __restrict__ Q, const float* __restrict__ K,
                         const float* __restrict__ Wq, const float* __restrict__ Wk,
                         const float* __restrict__ Wv, const float* __restrict__ Wo)
{
    int s = blockIdx.y;
    int i = blockIdx.x * blockDim.x + threadIdx.x;   // 0..SEGP-1
    const float* src;
    unsigned *hi, *lo;
    int off = 0;
    switch (s) {
        case 0: src = Q;  hi = g_Qihi; lo = g_Qilo; break;
        case 1: src = Q;  hi = g_Qihi; lo = g_Qilo; off = SEGP; break;
        case 2: src = K;  hi = g_Kihi; lo = g_Kilo; break;
        case 3: src = K;  hi = g_Kihi; lo = g_Kilo; off = SEGP; break;
        case 4: src = Wq; hi = g_wqhi; lo = g_wqlo; break;
        case 5: src = Wk; hi = g_wkhi; lo = g_wklo; break;
        case 6: src = Wv; hi = g_wvhi; lo = g_wvlo; break;
        default: src = Wo; hi = g_wohi; lo = g_wolo; break;
    }
    float2 v = ((const float2*)src)[off + i];
    unsigned h, l;
    split_pair(v.x, v.y, h, l);
    hi[off + i] = h; lo[off + i] = l;
}

// ---------------------------------------------------------------------------
// GEMM: C[2048,1024] = A @ B^T + bias.  bf16x2 3-mma split (hh, hl, lh).
// BM=128 BN=128 BK=32, 256 thr, 8 warps (2m x 4n), warp tile 64x32.
// which=0 (qkv fused, blockIdx.z selects):
//   z=0: A=Qi,B=wq  -> g_q fp32
//   z=1: A=Ki,B=wk  -> g_khi/g_klo planes
//   z=2: A=Ki,B=wv  -> g_vthi/g_vtlo TRANSPOSED planes (shfl-pair epilogue)
// which=1: A=ohi/olo, B=wo -> out = g_o + relu(acc+bo)   (fp32)
// ---------------------------------------------------------------------------
#define GLD 20
#define ABUF (128 * GLD)
#define GEMM_SMEM (8 * ABUF * 4)     // 81920 B

__global__ __launch_bounds__(256) void gemm_all(
    const float* __restrict__ bq, const float* __restrict__ bk,
    const float* __restrict__ bv, const float* __restrict__ bo,
    float* __restrict__ outWo, int which)
{
    extern __shared__ unsigned smu[];
    const unsigned sbase = (unsigned)__cvta_generic_to_shared(smu);

    const int tid  = threadIdx.x;
    const int warp = tid >> 5;
    const int lane = tid & 31;
    const int g = lane >> 2;
    const int q = lane & 3;
    const int wm = warp & 1;
    const int wn = warp >> 1;
    const int rowBase = blockIdx.y * 128;
    const int colBase = blockIdx.x * 128;

    const unsigned *Ahi, *Alo, *Bhi, *Blo;
    const float* bias;
    int mode;                        // 0 fp32, 1 planes, 2 resid+relu, 3 vt planes
    if (which == 1) {
        Ahi = g_ohi; Alo = g_olo; Bhi = g_wohi; Blo = g_wolo;
        bias = bo; mode = 2;
    } else if (blockIdx.z == 0) {
        Ahi = g_Qihi; Alo = g_Qilo; Bhi = g_wqhi; Blo = g_wqlo;
        bias = bq; mode = 0;
    } else if (blockIdx.z == 1) {
        Ahi = g_Kihi; Alo = g_Kilo; Bhi = g_wkhi; Blo = g_wklo;
        bias = bk; mode = 1;
    } else {
        Ahi = g_Kihi; Alo = g_Kilo; Bhi = g_wvhi; Blo = g_wvlo;
        bias = bv; mode = 3;
    }

    auto issue = [&](int kt) {
        int buf = kt & 1;
        const unsigned* srcs[4] = {Ahi, Alo, Bhi, Blo};
#pragma unroll
        for (int p = 0; p < 4; p++) {
            int base = (p < 2) ? rowBase : colBase;
            unsigned soff = ((p < 2 ? buf * 2 + p : 4 + buf * 2 + (p - 2)) * ABUF);
#pragma unroll
            for (int u = 0; u < 2; u++) {
                int e = tid + u * 256;
                int row = e >> 2, ch = (e & 3) * 4;
                cp16(sbase + (soff + row * GLD + ch) * 4,
                     srcs[p] + (size_t)(base + row) * PD + kt * 16 + ch);
            }
        }
        CP_COMMIT;
    };

    float acc[16][4];
#pragma unroll
    for (int i = 0; i < 16; i++)
#pragma unroll
        for (int j = 0; j < 4; j++) acc[i][j] = 0.f;

    issue(0);
    const int NKT = DIM / 32;
    for (int kt = 0; kt < NKT; kt++) {
        if (kt + 1 < NKT) { issue(kt + 1); CP_WAIT1; }
        else              { CP_WAIT0; }
        __syncthreads();
        int buf = kt & 1;
        const unsigned* Ah = smu + (buf * 2 + 0) * ABUF;
        const unsigned* Al = smu + (buf * 2 + 1) * ABUF;
        const unsigned* Bh = smu + (4 + buf * 2 + 0) * ABUF;
        const unsigned* Bl = smu + (4 + buf * 2 + 1) * ABUF;

#pragma unroll
        for (int ks = 0; ks < 2; ks++) {
            int pb = ks * 8;
            unsigned ah[4][4], al[4][4];
#pragma unroll
            for (int mt = 0; mt < 4; mt++) {
                int r0 = wm * 64 + mt * 16 + g;
                ah[mt][0] = Ah[r0 * GLD + pb + q];
                ah[mt][1] = Ah[(r0 + 8) * GLD + pb + q];
                ah[mt][2] = Ah[r0 * GLD + pb + q + 4];
                ah[mt][3] = Ah[(r0 + 8) * GLD + pb + q + 4];
                al[mt][0] = Al[r0 * GLD + pb + q];
                al[mt][1] = Al[(r0 + 8) * GLD + pb + q];
                al[mt][2] = Al[r0 * GLD + pb + q + 4];
                al[mt][3] = Al[(r0 + 8) * GLD + pb + q + 4];
            }
            unsigned bh[4][2], bl[4][2];
#pragma unroll
            for (int nt = 0; nt < 4; nt++) {
                int n0 = wn * 32 + nt * 8 + g;
                bh[nt][0] = Bh[n0 * GLD + pb + q];
                bh[nt][1] = Bh[n0 * GLD + pb + q + 4];
                bl[nt][0] = Bl[n0 * GLD + pb + q];
                bl[nt][1] = Bl[n0 * GLD + pb + q + 4];
            }
#pragma unroll
            for (int mt = 0; mt < 4; mt++)
#pragma unroll
                for (int nt = 0; nt < 4; nt++) {
                    mma_bf16(acc[mt * 4 + nt], ah[mt], bh[nt][0], bh[nt][1]);
                    mma_bf16(acc[mt * 4 + nt], ah[mt], bl[nt][0], bl[nt][1]);
                    mma_bf16(acc[mt * 4 + nt], al[mt], bh[nt][0], bh[nt][1]);
                }
        }
        __syncthreads();
    }

    // epilogue
#pragma unroll
    for (int mt = 0; mt < 4; mt++) {
#pragma unroll
        for (int nt = 0; nt < 4; nt++) {
            float* a = acc[mt * 4 + nt];
            int row = rowBase + wm * 64 + mt * 16 + g;
            int col = colBase + wn * 32 + nt * 8 + 2 * q;
            float b0 = bias[col], b1 = bias[col + 1];
#pragma unroll
            for (int half = 0; half < 2; half++) {
                int r = row + half * 8;
                float v0 = a[half * 2 + 0] + b0;
                float v1 = a[half * 2 + 1] + b1;
                if (mode == 3) {
                    // transposed vt planes: pair rows (r, r+1) via g<->g^1
                    float p0 = __shfl_xor_sync(0xffffffffu, v0, 4);
                    float p1 = __shfl_xor_sync(0xffffffffu, v1, 4);
                    if (!(g & 1)) {
                        unsigned h, l;
                        split_pair(v0, p0, h, l);
                        g_vthi[(size_t)col * NKP + r / 2] = h;
                        g_vtlo[(size_t)col * NKP + r / 2] = l;
                        split_pair(v1, p1, h, l);
                        g_vthi[(size_t)(col + 1) * NKP + r / 2] = h;
                        g_vtlo[(size_t)(col + 1) * NKP + r / 2] = l;
                    }
                } else if (mode == 1) {
                    unsigned h, l;
                    split_pair(v0, v1, h, l);
                    g_khi[(size_t)r * PD + col / 2] = h;
                    g_klo[(size_t)r * PD + col / 2] = l;
                } else if (mode == 2) {
                    const float* rp = g_o + (size_t)r * DIM + col;
                    *(float2*)(outWo + (size_t)r * DIM + col) =
                        make_float2(rp[0] + fmaxf(v0, 0.f), rp[1] + fmaxf(v1, 0.f));
                } else {
                    *(float2*)(g_q + (size_t)r * DIM + col) = make_float2(v0, v1);
                }
            }
        }
    }
}

// ---------------------------------------------------------------------------
// Attention (proven R4): mma.sync bf16x2 split, FMA-only exp, online softmax,
// /32-after-softmax, +Q residual, scrambled-reshape epilogue.
// ---------------------------------------------------------------------------
#define PLD 36
#define PREG (128 * PLD)
#define KLD 36
#define KVT (64 * KLD)
#define KVOFF (2 * PREG)
#define ATTN_SMEM ((2 * PREG + 8 * KVT) * 4)

__global__ __launch_bounds__(256) void attn_bf16x2()
{
    extern __shared__ unsigned smu[];
    const unsigned sbase = (unsigned)__cvta_generic_to_shared(smu);
    unsigned* Phi = smu;
    unsigned* Plo = smu + PREG;
    float* Qst = (float*)smu;

    const int h  = blockIdx.y;
    const int q0 = blockIdx.x * 128;
    const int c0 = h * HD;
    const int tid  = threadIdx.x;
    const int warp = tid >> 5;
    const int lane = tid & 31;
    const int g = lane >> 2;
    const int q = lane & 3;
    const int wrow = warp * 16;

    auto issue = [&](int kb) {
        int buf = kb & 1;
        int k0 = kb * 64;
        const unsigned* srcs[4] = {g_khi, g_klo, g_vthi, g_vtlo};
#pragma unroll
        for (int p = 0; p < 4; p++) {
            unsigned soff = KVOFF + (buf * 4 + p) * KVT;
#pragma unroll
            for (int u = 0; u < 2; u++) {
                int e = tid + u * 256;
                int row = e >> 3, ch = (e & 7) * 4;
                size_t gidx = (p < 2)
                    ? (size_t)(k0 + row) * PD + h * 32 + ch
                    : (size_t)(c0 + row) * NKP + kb * 32 + ch;
                cp16(sbase + (soff + row * KLD + ch) * 4, srcs[p] + gidx);
            }
        }
        CP_COMMIT;
    };

    issue(0);

#pragma unroll
    for (int u = 0; u < 8; u++) {
        int f = tid + u * 256;
        int r = f >> 4, c4 = (f & 15) << 2;
        float4 a = *(const float4*)(g_q + (size_t)(q0 + r) * DIM + c0 + c4);
        *(float4*)&Qst[r * 68 + c4] = a;
    }
    __syncthreads();

    unsigned qh[4][4], ql[4][4];
#pragma unroll
    for (int s = 0; s < 4; s++) {
        int cb = s * 16 + 2 * q;
        float2 p00 = *(float2*)&Qst[(wrow + g) * 68 + cb];
        float2 p10 = *(float2*)&Qst[(wrow + g + 8) * 68 + cb];
        float2 p01 = *(float2*)&Qst[(wrow + g) * 68 + cb + 8];
        float2 p11 = *(float2*)&Qst[(wrow + g + 8) * 68 + cb + 8];
        split_pair(p00.x, p00.y, qh[s][0], ql[s][0]);
        split_pair(p10.x, p10.y, qh[s][1], ql[s][1]);
        split_pair(p01.x, p01.y, qh[s][2], ql[s][2]);
        split_pair(p11.x, p11.y, qh[s][3], ql[s][3]);
    }
    __syncthreads();

    float m0 = -1e30f, m1 = -1e30f, l0 = 0.f, l1 = 0.f;
    float oacc[8][4];
#pragma unroll
    for (int nt = 0; nt < 8; nt++)
#pragma unroll
        for (int j = 0; j < 4; j++) oacc[nt][j] = 0.f;

    const int NKB = NK / 64;
    for (int kb = 0; kb < NKB; kb++) {
        if (kb + 1 < NKB) { issue(kb + 1); CP_WAIT1; }
        else              { CP_WAIT0; }
        __syncthreads();
        int buf = kb & 1;
        const unsigned* Kh = smu + KVOFF + (buf * 4 + 0) * KVT;
        const unsigned* Kl = smu + KVOFF + (buf * 4 + 1) * KVT;
        const unsigned* Vh = smu + KVOFF + (buf * 4 + 2) * KVT;
        const unsigned* Vl = smu + KVOFF + (buf * 4 + 3) * KVT;

        float sacc[8][4];
#pragma unroll
        for (int nt = 0; nt < 8; nt++)
#pragma unroll
            for (int j = 0; j < 4; j++) sacc[nt][j] = 0.f;
#pragma unroll
        for (int ks = 0; ks < 4; ks++) {
            int pb = ks * 8;
#pragma unroll
            for (int nt = 0; nt < 8; nt++) {
                int kr = nt * 8 + g;
                unsigned bh0 = Kh[kr * KLD + pb + q];
                unsigned bh1 = Kh[kr * KLD + pb + q + 4];
                unsigned bl0 = Kl[kr * KLD + pb + q];
                unsigned bl1 = Kl[kr * KLD + pb + q + 4];
                mma_bf16(sacc[nt], qh[ks], bh0, bh1);
                mma_bf16(sacc[nt], qh[ks], bl0, bl1);
                mma_bf16(sacc[nt], ql[ks], bh0, bh1);
            }
        }

        float mx0 = -1e30f, mx1 = -1e30f;
#pragma unroll
        for (int nt = 0; nt < 8; nt++) {
            mx0 = fmaxf(mx0, fmaxf(sacc[nt][0], sacc[nt][1]));
            mx1 = fmaxf(mx1, fmaxf(sacc[nt][2], sacc[nt][3]));
        }
        mx0 = fmaxf(mx0, __shfl_xor_sync(0xffffffffu, mx0, 1));
        mx0 = fmaxf(mx0, __shfl_xor_sync(0xffffffffu, mx0, 2));
        mx1 = fmaxf(mx1, __shfl_xor_sync(0xffffffffu, mx1, 1));
        mx1 = fmaxf(mx1, __shfl_xor_sync(0xffffffffu, mx1, 2));
        float nm0 = fmaxf(m0, mx0), nm1 = fmaxf(m1, mx1);
        float al0 = fexp(m0 - nm0), al1 = fexp(m1 - nm1);
        m0 = nm0; m1 = nm1;

        float s0 = 0.f, s1 = 0.f;
#pragma unroll
        for (int nt = 0; nt < 8; nt++) {
            sacc[nt][0] = fexp(sacc[nt][0] - nm0);
            sacc[nt][1] = fexp(sacc[nt][1] - nm0);
            sacc[nt][2] = fexp(sacc[nt][2] - nm1);
            sacc[nt][3] = fexp(sacc[nt][3] - nm1);
            s0 += sacc[nt][0] + sacc[nt][1];
            s1 += sacc[nt][2] + sacc[nt][3];
        }
        s0 += __shfl_xor_sync(0xffffffffu, s0, 1);
        s0 += __shfl_xor_sync(0xffffffffu, s0, 2);
        s1 += __shfl_xor_sync(0xffffffffu, s1, 1);
        s1 += __shfl_xor_sync(0xffffffffu, s1, 2);
        l0 = l0 * al0 + s0;
        l1 = l1 * al1 + s1;
#pragma unroll
        for (int nt = 0; nt < 8; nt++) {
            oacc[nt][0] *= al0; oacc[nt][1] *= al0;
            oacc[nt][2] *= al1; oacc[nt][3] *= al1;
        }

        __syncwarp();
#pragma unroll
        for (int nt = 0; nt < 8; nt++) {
            unsigned h2, l2;
            split_pair(sacc[nt][0], sacc[nt][1], h2, l2);
            Phi[(wrow + g) * PLD + nt * 4 + q] = h2;
            Plo[(wrow + g) * PLD + nt * 4 + q] = l2;
            split_pair(sacc[nt][2], sacc[nt][3], h2, l2);
            Phi[(wrow + g + 8) * PLD + nt * 4 + q] = h2;
            Plo[(wrow + g + 8) * PLD + nt * 4 + q] = l2;
        }
        __syncwarp();

#pragma unroll
        for (int ks = 0; ks < 4; ks++) {
            int pb = ks * 8;
            unsigned pah[4], pal[4];
            pah[0] = Phi[(wrow + g) * PLD + pb + q];
            pah[1] = Phi[(wrow + g + 8) * PLD + pb + q];
            pah[2] = Phi[(wrow + g) * PLD + pb + q + 4];
            pah[3] = Phi[(wrow + g + 8) * PLD + pb + q + 4];
            pal[0] = Plo[(wrow + g) * PLD + pb + q];
            pal[1] = Plo[(wrow + g + 8) * PLD + pb + q];
            pal[2] = Plo[(wrow + g) * PLD + pb + q + 4];
            pal[3] = Plo[(wrow + g + 8) * PLD + pb + q + 4];
#pragma unroll
            for (int nt = 0; nt < 8; nt++) {
                int dr = nt * 8 + g;
                unsigned bh0 = Vh[dr * KLD + pb + q];
                unsigned bh1 = Vh[dr * KLD + pb + q + 4];
                unsigned bl0 = Vl[dr * KLD + pb + q];
                unsigned bl1 = Vl[dr * KLD + pb + q + 4];
                mma_bf16(oacc[nt], pah, bh0, bh1);
                mma_bf16(oacc[nt], pah, bl0, bl1);
                mma_bf16(oacc[nt], pal, bh0, bh1);
            }
        }
        __syncthreads();
    }

    float inv0 = 1.f / (l0 * 32.f);
    float inv1 = 1.f / (l1 * 32.f);
    int n0r = q0 + wrow + g;
    int n1r = n0r + 8;
    int dr0 = h * 128 + (n0r >> 4), dc0 = (n0r & 15) * 64;
    int dr1 = h * 128 + (n1r >> 4), dc1 = (n1r & 15) * 64;
#pragma unroll
    for (int nt = 0; nt < 8; nt++) {
        int c = nt * 8 + 2 * q;
        float2 qr0 = *(const float2*)(g_q + (size_t)n0r * DIM + c0 + c);
        float2 qr1 = *(const float2*)(g_q + (size_t)n1r * DIM + c0 + c);
        float o0x = qr0.x + oacc[nt][0] * inv0;
        float o0y = qr0.y + oacc[nt][1] * inv0;
        float o1x = qr1.x + oacc[nt][2] * inv1;
        float o1y = qr1.y + oacc[nt][3] * inv1;
        *(float2*)(g_o + (size_t)dr0 * DIM + dc0 + c) = make_float2(o0x, o0y);
        *(float2*)(g_o + (size_t)dr1 * DIM + dc1 + c) = make_float2(o1x, o1y);
        unsigned hh, ll;
        split_pair(o0x, o0y, hh, ll);
        g_ohi[(size_t)dr0 * PD + (dc0 + c) / 2] = hh;
        g_olo[(size_t)dr0 * PD + (dc0 + c) / 2] = ll;
        split_pair(o1x, o1y, hh, ll);
        g_ohi[(size_t)dr1 * PD + (dc1 + c) / 2] = hh;
        g_olo[(size_t)dr1 * PD + (dc1 + c) / 2] = ll;
    }
}

// ---------------------------------------------------------------------------
extern "C" void kernel_launch(void* const* d_in, const int* in_sizes, int n_in,
                              void* d_out, int out_size)
{
    const float* Q  = (const float*)d_in[0];
    const float* K  = (const float*)d_in[1];
    const float* Wq = (const float*)d_in[2];
    const float* bq = (const float*)d_in[3];
    const float* Wk = (const float*)d_in[4];
    const float* bk = (const float*)d_in[5];
    const float* Wv = (const float*)d_in[6];
    const float* bv = (const float*)d_in[7];
    const float* Wo = (const float*)d_in[8];
    const float* bo = (const float*)d_in[9];
    float* out = (float*)d_out;

    cudaFuncSetAttribute(gemm_all,    cudaFuncAttributeMaxDynamicSharedMemorySize, GEMM_SMEM);
    cudaFuncSetAttribute(attn_bf16x2, cudaFuncAttributeMaxDynamicSharedMemorySize, ATTN_SMEM);

    // 1. pack everything (8 x 512K pairs)
    pack_all<<<dim3(SEGP / 256, 8), 256>>>(Q, K, Wq, Wk, Wv, Wo);

    // 2. fused q/k/v GEMMs (z: 0=q fp32, 1=k planes, 2=vt transposed planes)
    gemm_all<<<dim3(DIM / 128, NQ / 128, 3), 256, GEMM_SMEM>>>(bq, bk, bv, bo, out, 0);

    // 3. attention
    attn_bf16x2<<<dim3(NQ / 128, NHEAD), 256, ATTN_SMEM>>>();

    // 4. output projection + relu residual
    gemm_all<<<dim3(DIM / 128, NQ / 128, 1), 256, GEMM_SMEM>>>(bq, bk, bv, bo, out, 1);
}

// round 7
// speedup vs baseline: 2.8821x; 1.0679x over previous
#include <cuda_runtime.h>
#include <cuda_bf16.h>
#include <math.h>

// ---------------------------------------------------------------------------
// MAB block, bf16x2 split-precision mma.sync + ldmatrix fragment loads.
// (tcgen05 blocked: harness compiles via compute_103/sm_103 without 'a'.)
//   q = Q@Wq^T+bq ; k = K@Wk^T+bk ; v = K@Wv^T+bv
//   per head h (16 heads, d=64):
//     O_[h,n,:] = Q_[h,n,:] + (softmax(Q_h K_h^T)/32 @ V_h)[n,:]
//   reshape quirk: O[r,j] = O_[ r/128, (r%128)*16 + j/64, j%64 ]
//   out = O + relu(O@Wo^T + bo)
// ---------------------------------------------------------------------------

#define NQ 2048
#define NK 2048
#define DIM 1024
#define NHEAD 16
#define HD 64
#define PD 512          // u32 pairs per 1024-wide row
#define NKP 1024        // u32 pairs per 2048-wide row (vt)

// fp32 scratch
__device__ float g_q[NQ * DIM];
__device__ float g_o[NQ * DIM];
// bf16 hi/lo planes (u32 = bf16x2 pair, element0 = even index)
__device__ unsigned g_Qihi[NQ * PD],  g_Qilo[NQ * PD];
__device__ unsigned g_Kihi[NK * PD],  g_Kilo[NK * PD];
__device__ unsigned g_wqhi[DIM * PD], g_wqlo[DIM * PD];
__device__ unsigned g_wkhi[DIM * PD], g_wklo[DIM * PD];
__device__ unsigned g_wvhi[DIM * PD], g_wvlo[DIM * PD];
__device__ unsigned g_wohi[DIM * PD], g_wolo[DIM * PD];
__device__ unsigned g_khi[NK * PD],   g_klo[NK * PD];
__device__ unsigned g_vthi[DIM * NKP], g_vtlo[DIM * NKP];
__device__ unsigned g_ohi[NQ * PD],   g_olo[NQ * PD];

// ---------------------------------------------------------------------------
__device__ __forceinline__ void split_pair(float a, float b,
                                           unsigned& hi, unsigned& lo) {
    unsigned h;
    asm("cvt.rn.bf16x2.f32 %0, %1, %2;" : "=r"(h) : "f"(b), "f"(a));
    float ha = __uint_as_float(h << 16);
    float hb = __uint_as_float(h & 0xffff0000u);
    unsigned l;
    float ra = a - ha, rb = b - hb;
    asm("cvt.rn.bf16x2.f32 %0, %1, %2;" : "=r"(l) : "f"(rb), "f"(ra));
    hi = h; lo = l;
}

__device__ __forceinline__ void mma_bf16(float* c, const unsigned* a,
                                         unsigned b0, unsigned b1) {
    asm volatile(
        "mma.sync.aligned.m16n8k16.row.col.f32.bf16.bf16.f32 "
        "{%0,%1,%2,%3},{%4,%5,%6,%7},{%8,%9},{%0,%1,%2,%3};"
        : "+f"(c[0]), "+f"(c[1]), "+f"(c[2]), "+f"(c[3])
        : "r"(a[0]), "r"(a[1]), "r"(a[2]), "r"(a[3]), "r"(b0), "r"(b1));
}

__device__ __forceinline__ void ldsm4(unsigned* r, unsigned addr) {
    asm volatile("ldmatrix.sync.aligned.m8n8.x4.shared.b16 {%0,%1,%2,%3}, [%4];"
        : "=r"(r[0]), "=r"(r[1]), "=r"(r[2]), "=r"(r[3]) : "r"(addr));
}

// e^x via FMA-only exp2 (no MUFU). Valid x <= 0 (clamped at -80).
__device__ __forceinline__ float fexp(float x) {
    float z = fmaxf(x, -80.f) * 1.44269504f;
    float t = z + 12582912.0f;
    int   r = __float_as_int(t) - 0x4B400000;
    float f = z - (t - 12582912.0f);
    float p = 1.0f + f * (0.69314718f + f * (0.24022650f + f * (0.05550411f
                  + f * (0.00961804f + f * 0.00133336f))));
    return __int_as_float(__float_as_int(p) + (r << 23));
}

__device__ __forceinline__ void cp16(unsigned dst, const void* src) {
    asm volatile("cp.async.cg.shared.global [%0], [%1], 16;" :: "r"(dst), "l"(src));
}
#define CP_COMMIT asm volatile("cp.async.commit_group;")
#define CP_WAIT1  asm volatile("cp.async.wait_group 1;")
#define CP_WAIT0  asm volatile("cp.async.wait_group 0;")

// ---------------------------------------------------------------------------
// Fused pack: 8 uniform segments of 512K float2-pairs each.
// ---------------------------------------------------------------------------
#define SEGP 524288
__global__ void pack_all(const float* __restrict__ Q, const float* __restrict__ K,
                         const float* __restrict__ Wq, const float* __restrict__ Wk,
                         const float* __restrict__ Wv, const float* __restrict__ Wo)
{
    int s = blockIdx.y;
    int i = blockIdx.x * blockDim.x + threadIdx.x;
    const float* src;
    unsigned *hi, *lo;
    int off = 0;
    switch (s) {
        case 0: src = Q;  hi = g_Qihi; lo = g_Qilo; break;
        case 1: src = Q;  hi = g_Qihi; lo = g_Qilo; off = SEGP; break;
        case 2: src = K;  hi = g_Kihi; lo = g_Kilo; break;
        case 3: src = K;  hi = g_Kihi; lo = g_Kilo; off = SEGP; break;
        case 4: src = Wq; hi = g_wqhi; lo = g_wqlo; break;
        case 5: src = Wk; hi = g_wkhi; lo = g_wklo; break;
        case 6: src = Wv; hi = g_wvhi; lo = g_wvlo; break;
        default: src = Wo; hi = g_wohi; lo = g_wolo; break;
    }
    float2 v = ((const float2*)src)[off + i];
    unsigned h, l;
    split_pair(v.x, v.y, h, l);
    hi[off + i] = h; lo[off + i] = l;
}

// ---------------------------------------------------------------------------
// GEMM: C[2048,1024] = A @ B^T + bias.  bf16x2 3-mma split (hh, hl, lh).
// ldmatrix.x4 fragment loads. BM=BN=128, BK=32, 8 warps (2m x 4n).
// which=0 (qkv fused, z selects): z=0 q fp32, z=1 k planes, z=2 vt planes
// which=1: out = g_o + relu(acc+bo)
// ---------------------------------------------------------------------------
#define GLD 20
#define ABUF (128 * GLD)
#define GEMM_SMEM (8 * ABUF * 4)     // 81920 B

__global__ __launch_bounds__(256) void gemm_all(
    const float* __restrict__ bq, const float* __restrict__ bk,
    const float* __restrict__ bv, const float* __restrict__ bo,
    float* __restrict__ outWo, int which)
{
    extern __shared__ unsigned smu[];
    const unsigned sbase = (unsigned)__cvta_generic_to_shared(smu);

    const int tid  = threadIdx.x;
    const int warp = tid >> 5;
    const int lane = tid & 31;
    const int g = lane >> 2;
    const int q = lane & 3;
    const int wm = warp & 1;
    const int wn = warp >> 1;
    const int rowBase = blockIdx.y * 128;
    const int colBase = blockIdx.x * 128;

    // ldmatrix lane addressing
    const int lrowA = lane & 15;               // A: row within 16
    const int lcolA = (lane >> 4) * 4;         // A: u32 col select (0 or 4)
    const int btile = lane >> 4;               // B: tile select within pair
    const int browB = lane & 7;
    const int bcolB = ((lane >> 3) & 1) * 4;

    const unsigned *Ahi, *Alo, *Bhi, *Blo;
    const float* bias;
    int mode;                        // 0 fp32, 1 planes, 2 resid+relu, 3 vt planes
    if (which == 1) {
        Ahi = g_ohi; Alo = g_olo; Bhi = g_wohi; Blo = g_wolo;
        bias = bo; mode = 2;
    } else if (blockIdx.z == 0) {
        Ahi = g_Qihi; Alo = g_Qilo; Bhi = g_wqhi; Blo = g_wqlo;
        bias = bq; mode = 0;
    } else if (blockIdx.z == 1) {
        Ahi = g_Kihi; Alo = g_Kilo; Bhi = g_wkhi; Blo = g_wklo;
        bias = bk; mode = 1;
    } else {
        Ahi = g_Kihi; Alo = g_Kilo; Bhi = g_wvhi; Blo = g_wvlo;
        bias = bv; mode = 3;
    }

    auto issue = [&](int kt) {
        int buf = kt & 1;
        const unsigned* srcs[4] = {Ahi, Alo, Bhi, Blo};
#pragma unroll
        for (int p = 0; p < 4; p++) {
            int base = (p < 2) ? rowBase : colBase;
            unsigned soff = ((p < 2 ? buf * 2 + p : 4 + buf * 2 + (p - 2)) * ABUF);
#pragma unroll
            for (int u = 0; u < 2; u++) {
                int e = tid + u * 256;
                int row = e >> 2, ch = (e & 3) * 4;
                cp16(sbase + (soff + row * GLD + ch) * 4,
                     srcs[p] + (size_t)(base + row) * PD + kt * 16 + ch);
            }
        }
        CP_COMMIT;
    };

    // per-warp ldmatrix base offsets (byte offsets from sbase)
    const unsigned aLane = ((wm * 64 + lrowA) * GLD + lcolA) * 4;
    const unsigned bLane = ((wn * 32 + btile * 8 + browB) * GLD + bcolB) * 4;

    float acc[16][4];
#pragma unroll
    for (int i = 0; i < 16; i++)
#pragma unroll
        for (int j = 0; j < 4; j++) acc[i][j] = 0.f;

    issue(0);
    const int NKT = DIM / 32;
    for (int kt = 0; kt < NKT; kt++) {
        if (kt + 1 < NKT) { issue(kt + 1); CP_WAIT1; }
        else              { CP_WAIT0; }
        __syncthreads();
        int buf = kt & 1;
        const unsigned aBase = sbase + (buf * 2) * ABUF * 4 + aLane;
        const unsigned bBase = sbase + (4 + buf * 2) * ABUF * 4 + bLane;

#pragma unroll
        for (int ks = 0; ks < 2; ks++) {
            int pb = ks * 8;
            unsigned ah[4][4], al[4][4];
#pragma unroll
            for (int mt = 0; mt < 4; mt++) {
                unsigned ao = aBase + (mt * 16 * GLD + pb) * 4;
                ldsm4(ah[mt], ao);
                ldsm4(al[mt], ao + ABUF * 4);
            }
            unsigned bh[2][4], bl[2][4];
#pragma unroll
            for (int j = 0; j < 2; j++) {
                unsigned bo_ = bBase + (j * 16 * GLD + pb) * 4;
                ldsm4(bh[j], bo_);
                ldsm4(bl[j], bo_ + ABUF * 4);
            }
#pragma unroll
            for (int mt = 0; mt < 4; mt++)
#pragma unroll
                for (int nt = 0; nt < 4; nt++) {
                    unsigned b0h = bh[nt >> 1][(nt & 1) * 2];
                    unsigned b1h = bh[nt >> 1][(nt & 1) * 2 + 1];
                    unsigned b0l = bl[nt >> 1][(nt & 1) * 2];
                    unsigned b1l = bl[nt >> 1][(nt & 1) * 2 + 1];
                    mma_bf16(acc[mt * 4 + nt], ah[mt], b0h, b1h);
                    mma_bf16(acc[mt * 4 + nt], ah[mt], b0l, b1l);
                    mma_bf16(acc[mt * 4 + nt], al[mt], b0h, b1h);
                }
        }
        __syncthreads();
    }

    // epilogue
#pragma unroll
    for (int mt = 0; mt < 4; mt++) {
#pragma unroll
        for (int nt = 0; nt < 4; nt++) {
            float* a = acc[mt * 4 + nt];
            int row = rowBase + wm * 64 + mt * 16 + g;
            int col = colBase + wn * 32 + nt * 8 + 2 * q;
            float b0 = bias[col], b1 = bias[col + 1];
#pragma unroll
            for (int half = 0; half < 2; half++) {
                int r = row + half * 8;
                float v0 = a[half * 2 + 0] + b0;
                float v1 = a[half * 2 + 1] + b1;
                if (mode == 3) {
                    float p0 = __shfl_xor_sync(0xffffffffu, v0, 4);
                    float p1 = __shfl_xor_sync(0xffffffffu, v1, 4);
                    if (!(g & 1)) {
                        unsigned h, l;
                        split_pair(v0, p0, h, l);
                        g_vthi[(size_t)col * NKP + r / 2] = h;
                        g_vtlo[(size_t)col * NKP + r / 2] = l;
                        split_pair(v1, p1, h, l);
                        g_vthi[(size_t)(col + 1) * NKP + r / 2] = h;
                        g_vtlo[(size_t)(col + 1) * NKP + r / 2] = l;
                    }
                } else if (mode == 1) {
                    unsigned h, l;
                    split_pair(v0, v1, h, l);
                    g_khi[(size_t)r * PD + col / 2] = h;
                    g_klo[(size_t)r * PD + col / 2] = l;
                } else if (mode == 2) {
                    const float* rp = g_o + (size_t)r * DIM + col;
                    *(float2*)(outWo + (size_t)r * DIM + col) =
                        make_float2(rp[0] + fmaxf(v0, 0.f), rp[1] + fmaxf(v1, 0.f));
                } else {
                    *(float2*)(g_q + (size_t)r * DIM + col) = make_float2(v0, v1);
                }
            }
        }
    }
}

// ---------------------------------------------------------------------------
// Attention: mma.sync bf16x2 split + ldmatrix K/V loads + direct S->P
// fragment reuse (no P smem round-trip). FMA-only exp.
// smem (u32): Qst fp32 [128][68] = 8704, then {Kh,Kl,Vh,Vl}[64][36] x 2 bufs.
// ---------------------------------------------------------------------------
#define QREG 8704
#define KLD 36
#define KVT (64 * KLD)
#define ATTN_SMEM ((QREG + 8 * KVT) * 4)   // 108544 B

__global__ __launch_bounds__(256) void attn_bf16x2()
{
    extern __shared__ unsigned smu[];
    const unsigned sbase = (unsigned)__cvta_generic_to_shared(smu);
    float* Qst = (float*)smu;

    const int h  = blockIdx.y;
    const int q0 = blockIdx.x * 128;
    const int c0 = h * HD;
    const int tid  = threadIdx.x;
    const int warp = tid >> 5;
    const int lane = tid & 31;
    const int g = lane >> 2;
    const int q = lane & 3;
    const int wrow = warp * 16;

    const int btile = lane >> 4;
    const int browB = lane & 7;
    const int bcolB = ((lane >> 3) & 1) * 4;
    const unsigned kLane = sbase + (QREG + (btile * 8 + browB) * KLD + bcolB) * 4;

    auto issue = [&](int kb) {
        int buf = kb & 1;
        int k0 = kb * 64;
        const unsigned* srcs[4] = {g_khi, g_klo, g_vthi, g_vtlo};
#pragma unroll
        for (int p = 0; p < 4; p++) {
            unsigned soff = QREG + (buf * 4 + p) * KVT;
#pragma unroll
            for (int u = 0; u < 2; u++) {
                int e = tid + u * 256;
                int row = e >> 3, ch = (e & 7) * 4;
                size_t gidx = (p < 2)
                    ? (size_t)(k0 + row) * PD + h * 32 + ch
                    : (size_t)(c0 + row) * NKP + kb * 32 + ch;
                cp16(sbase + (soff + row * KLD + ch) * 4, srcs[p] + gidx);
            }
        }
        CP_COMMIT;
    };

    issue(0);

#pragma unroll
    for (int u = 0; u < 8; u++) {
        int f = tid + u * 256;
        int r = f >> 4, c4 = (f & 15) << 2;
        float4 a = *(const float4*)(g_q + (size_t)(q0 + r) * DIM + c0 + c4);
        *(float4*)&Qst[r * 68 + c4] = a;
    }
    __syncthreads();

    unsigned qh[4][4], ql[4][4];
#pragma unroll
    for (int s = 0; s < 4; s++) {
        int cb = s * 16 + 2 * q;
        float2 p00 = *(float2*)&Qst[(wrow + g) * 68 + cb];
        float2 p10 = *(float2*)&Qst[(wrow + g + 8) * 68 + cb];
        float2 p01 = *(float2*)&Qst[(wrow + g) * 68 + cb + 8];
        float2 p11 = *(float2*)&Qst[(wrow + g + 8) * 68 + cb + 8];
        split_pair(p00.x, p00.y, qh[s][0], ql[s][0]);
        split_pair(p10.x, p10.y, qh[s][1], ql[s][1]);
        split_pair(p01.x, p01.y, qh[s][2], ql[s][2]);
        split_pair(p11.x, p11.y, qh[s][3], ql[s][3]);
    }
    __syncthreads();

    float m0 = -1e30f, m1 = -1e30f, l0 = 0.f, l1 = 0.f;
    float oacc[8][4];
#pragma unroll
    for (int nt = 0; nt < 8; nt++)
#pragma unroll
        for (int j = 0; j < 4; j++) oacc[nt][j] = 0.f;

    const int NKB = NK / 64;
    for (int kb = 0; kb < NKB; kb++) {
        if (kb + 1 < NKB) { issue(kb + 1); CP_WAIT1; }
        else              { CP_WAIT0; }
        __syncthreads();
        int buf = kb & 1;
        const unsigned kBase = kLane + (buf * 4) * KVT * 4;

        // S = Q K^T (3-mma split), K frags via ldmatrix.x4 (2 tiles each)
        float sacc[8][4];
#pragma unroll
        for (int nt = 0; nt < 8; nt++)
#pragma unroll
            for (int j = 0; j < 4; j++) sacc[nt][j] = 0.f;
#pragma unroll
        for (int ks = 0; ks < 4; ks++) {
            int pb = ks * 8;
#pragma unroll
            for (int j = 0; j < 4; j++) {
                unsigned kh4[4], kl4[4];
                unsigned ko = kBase + (j * 16 * KLD + pb) * 4;
                ldsm4(kh4, ko);
                ldsm4(kl4, ko + KVT * 4);
                mma_bf16(sacc[2 * j],     qh[ks], kh4[0], kh4[1]);
                mma_bf16(sacc[2 * j],     qh[ks], kl4[0], kl4[1]);
                mma_bf16(sacc[2 * j],     ql[ks], kh4[0], kh4[1]);
                mma_bf16(sacc[2 * j + 1], qh[ks], kh4[2], kh4[3]);
                mma_bf16(sacc[2 * j + 1], qh[ks], kl4[2], kl4[3]);
                mma_bf16(sacc[2 * j + 1], ql[ks], kh4[2], kh4[3]);
            }
        }

        // online softmax (FMA-only exp)
        float mx0 = -1e30f, mx1 = -1e30f;
#pragma unroll
        for (int nt = 0; nt < 8; nt++) {
            mx0 = fmaxf(mx0, fmaxf(sacc[nt][0], sacc[nt][1]));
            mx1 = fmaxf(mx1, fmaxf(sacc[nt][2], sacc[nt][3]));
        }
        mx0 = fmaxf(mx0, __shfl_xor_sync(0xffffffffu, mx0, 1));
        mx0 = fmaxf(mx0, __shfl_xor_sync(0xffffffffu, mx0, 2));
        mx1 = fmaxf(mx1, __shfl_xor_sync(0xffffffffu, mx1, 1));
        mx1 = fmaxf(mx1, __shfl_xor_sync(0xffffffffu, mx1, 2));
        float nm0 = fmaxf(m0, mx0), nm1 = fmaxf(m1, mx1);
        float al0 = fexp(m0 - nm0), al1 = fexp(m1 - nm1);
        m0 = nm0; m1 = nm1;

        float s0 = 0.f, s1 = 0.f;
#pragma unroll
        for (int nt = 0; nt < 8; nt++) {
            sacc[nt][0] = fexp(sacc[nt][0] - nm0);
            sacc[nt][1] = fexp(sacc[nt][1] - nm0);
            sacc[nt][2] = fexp(sacc[nt][2] - nm1);
            sacc[nt][3] = fexp(sacc[nt][3] - nm1);
            s0 += sacc[nt][0] + sacc[nt][1];
            s1 += sacc[nt][2] + sacc[nt][3];
        }
        s0 += __shfl_xor_sync(0xffffffffu, s0, 1);
        s0 += __shfl_xor_sync(0xffffffffu, s0, 2);
        s1 += __shfl_xor_sync(0xffffffffu, s1, 1);
        s1 += __shfl_xor_sync(0xffffffffu, s1, 2);
        l0 = l0 * al0 + s0;
        l1 = l1 * al1 + s1;
#pragma unroll
        for (int nt = 0; nt < 8; nt++) {
            oacc[nt][0] *= al0; oacc[nt][1] *= al0;
            oacc[nt][2] *= al1; oacc[nt][3] *= al1;
        }

        // O += P V : P A-fragments built DIRECTLY from sacc (C-frag == A-frag)
#pragma unroll
        for (int ks = 0; ks < 4; ks++) {
            unsigned pah[4], pal[4];
            split_pair(sacc[2 * ks][0],     sacc[2 * ks][1],     pah[0], pal[0]);
            split_pair(sacc[2 * ks][2],     sacc[2 * ks][3],     pah[1], pal[1]);
            split_pair(sacc[2 * ks + 1][0], sacc[2 * ks + 1][1], pah[2], pal[2]);
            split_pair(sacc[2 * ks + 1][2], sacc[2 * ks + 1][3], pah[3], pal[3]);
            int pb = ks * 8;
#pragma unroll
            for (int j = 0; j < 4; j++) {
                unsigned vh4[4], vl4[4];
                unsigned vo = kBase + 2 * KVT * 4 + (j * 16 * KLD + pb) * 4;
                ldsm4(vh4, vo);
                ldsm4(vl4, vo + KVT * 4);
                mma_bf16(oacc[2 * j],     pah, vh4[0], vh4[1]);
                mma_bf16(oacc[2 * j],     pah, vl4[0], vl4[1]);
                mma_bf16(oacc[2 * j],     pal, vh4[0], vh4[1]);
                mma_bf16(oacc[2 * j + 1], pah, vh4[2], vh4[3]);
                mma_bf16(oacc[2 * j + 1], pah, vl4[2], vl4[3]);
                mma_bf16(oacc[2 * j + 1], pal, vh4[2], vh4[3]);
            }
        }
        __syncthreads();
    }

    float inv0 = 1.f / (l0 * 32.f);
    float inv1 = 1.f / (l1 * 32.f);
    int n0r = q0 + wrow + g;
    int n1r = n0r + 8;
    int dr0 = h * 128 + (n0r >> 4), dc0 = (n0r & 15) * 64;
    int dr1 = h * 128 + (n1r >> 4), dc1 = (n1r & 15) * 64;
#pragma unroll
    for (int nt = 0; nt < 8; nt++) {
        int c = nt * 8 + 2 * q;
        float2 qr0 = *(const float2*)(g_q + (size_t)n0r * DIM + c0 + c);
        float2 qr1 = *(const float2*)(g_q + (size_t)n1r * DIM + c0 + c);
        float o0x = qr0.x + oacc[nt][0] * inv0;
        float o0y = qr0.y + oacc[nt][1] * inv0;
        float o1x = qr1.x + oacc[nt][2] * inv1;
        float o1y = qr1.y + oacc[nt][3] * inv1;
        *(float2*)(g_o + (size_t)dr0 * DIM + dc0 + c) = make_float2(o0x, o0y);
        *(float2*)(g_o + (size_t)dr1 * DIM + dc1 + c) = make_float2(o1x, o1y);
        unsigned hh, ll;
        split_pair(o0x, o0y, hh, ll);
        g_ohi[(size_t)dr0 * PD + (dc0 + c) / 2] = hh;
        g_olo[(size_t)dr0 * PD + (dc0 + c) / 2] = ll;
        split_pair(o1x, o1y, hh, ll);
        g_ohi[(size_t)dr1 * PD + (dc1 + c) / 2] = hh;
        g_olo[(size_t)dr1 * PD + (dc1 + c) / 2] = ll;
    }
}

// ---------------------------------------------------------------------------
extern "C" void kernel_launch(void* const* d_in, const int* in_sizes, int n_in,
                              void* d_out, int out_size)
{
    const float* Q  = (const float*)d_in[0];
    const float* K  = (const float*)d_in[1];
    const float* Wq = (const float*)d_in[2];
    const float* bq = (const float*)d_in[3];
    const float* Wk = (const float*)d_in[4];
    const float* bk = (const float*)d_in[5];
    const float* Wv = (const float*)d_in[6];
    const float* bv = (const float*)d_in[7];
    const float* Wo = (const float*)d_in[8];
    const float* bo = (const float*)d_in[9];
    float* out = (float*)d_out;

    cudaFuncSetAttribute(gemm_all,    cudaFuncAttributeMaxDynamicSharedMemorySize, GEMM_SMEM);
    cudaFuncSetAttribute(attn_bf16x2, cudaFuncAttributeMaxDynamicSharedMemorySize, ATTN_SMEM);

    pack_all<<<dim3(SEGP / 256, 8), 256>>>(Q, K, Wq, Wk, Wv, Wo);
    gemm_all<<<dim3(DIM / 128, NQ / 128, 3), 256, GEMM_SMEM>>>(bq, bk, bv, bo, out, 0);
    attn_bf16x2<<<dim3(NQ / 128, NHEAD), 256, ATTN_SMEM>>>();
    gemm_all<<<dim3(DIM / 128, NQ / 128, 1), 256, GEMM_SMEM>>>(bq, bk, bv, bo, out, 1);
}